// round 7
// baseline (speedup 1.0000x reference)
#include <cuda_runtime.h>
#include <cuda_fp16.h>
#include <math.h>
#include <float.h>
#include <stdint.h>

// Problem constants (GAT_38585986187787)
#define MAX_NODES 100000
#define MAX_EDGES 1600000
#define D_IN 64
#define HEADS 4
#define HC 256   // HEADS * C_OUT
#define SCAN_B 1024
#define MAX_SCAN_BLOCKS 128

// smem strides in half2 (4B) units, bank-conflict-free fragment loads
#define SXP 36   // x tile:  bank = (4r + kk) % 32, distinct per 8x4 lanes
#define SWP 264  // W tile:  bank = (8kk + n) % 32, distinct per 4x8 lanes

// ---------------------------------------------------------------------------
// Device scratch
// ---------------------------------------------------------------------------
__device__ __half g_xlh[(size_t)MAX_NODES * HC];    // 51.2 MB   x @ W (fp16)
__device__ float g_asrc[MAX_NODES * HEADS];         // 1.6 MB
__device__ float g_adst[MAX_NODES * HEADS];         // 1.6 MB
__device__ int   g_cnt[MAX_NODES];                  // in-degree counts
__device__ int   g_off[MAX_NODES + 1];              // CSR offsets (by dst)
__device__ int   g_cur[MAX_NODES];                  // scatter cursors
__device__ int   g_srclist[MAX_EDGES];              // src id per CSR slot
__device__ int   g_bsum[MAX_SCAN_BLOCKS];           // scan block sums
__device__ int   g_bpre[MAX_SCAN_BLOCKS];           // scan block prefixes
__device__ int   g_is64;                            // edge_index dtype flag

__device__ __forceinline__ long long load_edge(const void* ei, int is64, size_t idx) {
    if (is64) return ((const long long*)ei)[idx];
    return (long long)(((const int*)ei)[idx]);
}

__device__ __forceinline__ float leaky(float v) {
    return (v >= 0.f) ? v : 0.2f * v;
}

// ---------------------------------------------------------------------------
// 1. Init (+ fused dtype detect): zero degree counters
// ---------------------------------------------------------------------------
__global__ void init_kernel(const void* ei, int n) {
    int idx = blockIdx.x * blockDim.x + threadIdx.x;
    if (idx == 0) {
        const unsigned long long* p = (const unsigned long long*)ei;
        bool ok = true;
#pragma unroll
        for (int i = 0; i < 16; i++) ok = ok && (p[i] < (unsigned long long)MAX_NODES);
        g_is64 = ok ? 1 : 0;
    }
    if (idx < n) g_cnt[idx] = 0;
}

// ---------------------------------------------------------------------------
// 2. Count in-degrees (2 edges per thread)
// ---------------------------------------------------------------------------
__global__ void count_kernel(const void* __restrict__ ei, int E) {
    int e = (blockIdx.x * blockDim.x + threadIdx.x) * 2;
    if (e >= E) return;
    int is64 = g_is64;
    if (e + 1 < E) {
        int d0, d1;
        if (is64) {
            longlong2 p = *(const longlong2*)((const long long*)ei + (size_t)E + e);
            d0 = (int)p.x; d1 = (int)p.y;
        } else {
            int2 p = *(const int2*)((const int*)ei + (size_t)E + e);
            d0 = p.x; d1 = p.y;
        }
        atomicAdd(&g_cnt[d0], 1);
        atomicAdd(&g_cnt[d1], 1);
    } else {
        int d = (int)load_edge(ei, is64, (size_t)E + e);
        atomicAdd(&g_cnt[d], 1);
    }
}

// ---------------------------------------------------------------------------
// 3a. Block-local exclusive scan (shfl-based), block sums to g_bsum
// ---------------------------------------------------------------------------
__global__ void scan1_kernel(int N) {
    int t = threadIdx.x;
    int i = blockIdx.x * SCAN_B + t;
    int lane = t & 31, wid = t >> 5;

    int v = (i < N) ? g_cnt[i] : 0;
    int x = v;
#pragma unroll
    for (int off = 1; off < 32; off <<= 1) {
        int u = __shfl_up_sync(0xffffffffu, x, off);
        if (lane >= off) x += u;
    }
    __shared__ int wsum[32];
    if (lane == 31) wsum[wid] = x;
    __syncthreads();
    if (wid == 0) {
        int y = wsum[lane];
#pragma unroll
        for (int off = 1; off < 32; off <<= 1) {
            int u = __shfl_up_sync(0xffffffffu, y, off);
            if (lane >= off) y += u;
        }
        wsum[lane] = y;
    }
    __syncthreads();
    int base = (wid > 0) ? wsum[wid - 1] : 0;
    int incl = base + x;
    if (i < N) g_off[i] = incl - v;
    if (t == SCAN_B - 1) g_bsum[blockIdx.x] = incl;
}

// ---------------------------------------------------------------------------
// 3b. Scan the block sums (nb <= 128), one block of 128 threads
// ---------------------------------------------------------------------------
__global__ void scan2_kernel(int nb, int N, int E) {
    int t = threadIdx.x, lane = t & 31, wid = t >> 5;
    int v = (t < nb) ? g_bsum[t] : 0;
    int x = v;
#pragma unroll
    for (int off = 1; off < 32; off <<= 1) {
        int u = __shfl_up_sync(0xffffffffu, x, off);
        if (lane >= off) x += u;
    }
    __shared__ int ws[4];
    __shared__ int wpre[4];
    if (lane == 31) ws[wid] = x;
    __syncthreads();
    if (t == 0) {
        int s = 0;
#pragma unroll
        for (int k = 0; k < 4; k++) { wpre[k] = s; s += ws[k]; }
    }
    __syncthreads();
    int incl = wpre[wid] + x;
    if (t < nb) g_bpre[t] = incl - v;
    if (t == 0) g_off[N] = E;
}

// ---------------------------------------------------------------------------
// 3c. Add block bases, emit cursors
// ---------------------------------------------------------------------------
__global__ void scan3_kernel(int N) {
    int i = blockIdx.x * SCAN_B + threadIdx.x;
    if (i < N) {
        int o = g_off[i] + g_bpre[blockIdx.x];
        g_off[i] = o;
        g_cur[i] = o;
    }
}

// ---------------------------------------------------------------------------
// 4. Scatter src ids into CSR slots (2 edges per thread)
// ---------------------------------------------------------------------------
__global__ void scatter_kernel(const void* __restrict__ ei, int E) {
    int e = (blockIdx.x * blockDim.x + threadIdx.x) * 2;
    if (e >= E) return;
    int is64 = g_is64;
    if (e + 1 < E) {
        int s0, s1, d0, d1;
        if (is64) {
            longlong2 ps = *(const longlong2*)((const long long*)ei + e);
            longlong2 pd = *(const longlong2*)((const long long*)ei + (size_t)E + e);
            s0 = (int)ps.x; s1 = (int)ps.y; d0 = (int)pd.x; d1 = (int)pd.y;
        } else {
            int2 ps = *(const int2*)((const int*)ei + e);
            int2 pd = *(const int2*)((const int*)ei + (size_t)E + e);
            s0 = ps.x; s1 = ps.y; d0 = pd.x; d1 = pd.y;
        }
        int p0 = atomicAdd(&g_cur[d0], 1);
        int p1 = atomicAdd(&g_cur[d1], 1);
        g_srclist[p0] = s0;
        g_srclist[p1] = s1;
    } else {
        int s = (int)load_edge(ei, is64, e);
        int d = (int)load_edge(ei, is64, (size_t)E + e);
        int pos = atomicAdd(&g_cur[d], 1);
        g_srclist[pos] = s;
    }
}

// ---------------------------------------------------------------------------
// 5. FP16 tensor-core GEMM (m16n8k16) + fused attention scores.
//    Block: 256 thr (8 warps), tile M=64, N=256, K=64. Warp grid 2(M) x 4(N);
//    warp wn owns head wn. Fragments are packed half2 -> 1 LDS.32 per reg.
//    fp32 accumulate; xl stored fp16.
// ---------------------------------------------------------------------------
__global__ void __launch_bounds__(256, 2)
gemm_kernel(const float* __restrict__ x, const float* __restrict__ W,
            const float* __restrict__ att_src,
            const float* __restrict__ att_dst, int n) {
    extern __shared__ uint32_t sm[];
    uint32_t* sA = sm;                 // 64 rows x SXP half2  (x tile)
    uint32_t* sB = sm + 64 * SXP;      // 32 kk-rows x SWP half2 (W, k-pairs packed)

    int t = threadIdx.x;
    int lane = t & 31;
    int wid = t >> 5;
    int wm = wid >> 2;        // 0..1
    int wn = wid & 3;         // 0..3 (head)
    int row0 = blockIdx.x * 64;

    // ---- Stage x tile (64x64) -> fp16 half2 pairs along k ----
#pragma unroll
    for (int i = 0; i < 4; i++) {
        int idx4 = t + i * 256;
        int r = idx4 >> 4, c4 = idx4 & 15;          // c = c4*4
        float4 v = make_float4(0.f, 0.f, 0.f, 0.f);
        if (row0 + r < n) v = *(const float4*)(x + (size_t)(row0 + r) * D_IN + c4 * 4);
        uint32_t* p = sA + r * SXP + c4 * 2;
        __half2 h0 = __floats2half2_rn(v.x, v.y);
        __half2 h1 = __floats2half2_rn(v.z, v.w);
        p[0] = *(uint32_t*)&h0;
        p[1] = *(uint32_t*)&h1;
    }

    // ---- Stage W (64x256) -> Wp[kk][n] = half2(W[2kk][n], W[2kk+1][n]) ----
    __half* sBh = (__half*)sB;
#pragma unroll
    for (int i = 0; i < 16; i++) {
        int idx4 = t + i * 256;
        int k = idx4 >> 6, c = (idx4 & 63) * 4;
        float4 v = *(const float4*)(W + (size_t)k * HC + c);
        int base = ((k >> 1) * SWP + c) * 2 + (k & 1);   // half index
        sBh[base + 0] = __float2half_rn(v.x);
        sBh[base + 2] = __float2half_rn(v.y);
        sBh[base + 4] = __float2half_rn(v.z);
        sBh[base + 6] = __float2half_rn(v.w);
    }
    __syncthreads();

    float acc[2][8][4];
#pragma unroll
    for (int mt = 0; mt < 2; mt++)
#pragma unroll
        for (int nt = 0; nt < 8; nt++)
#pragma unroll
            for (int k = 0; k < 4; k++) acc[mt][nt][k] = 0.f;

    int qr = lane >> 2;   // 0..7
    int ql = lane & 3;    // 0..3

#pragma unroll
    for (int kc = 0; kc < 4; kc++) {
        int kk0 = kc * 8;   // half2 offset along k
        // A frags: a0=(qr, k 2ql..), a1=(qr+8), a2=(qr, +8 cols), a3=(qr+8, +8)
        uint32_t a[2][4];
#pragma unroll
        for (int mt = 0; mt < 2; mt++) {
            int rb = wm * 32 + mt * 16 + qr;
            const uint32_t* pa = sA + rb * SXP + kk0 + ql;
            a[mt][0] = pa[0];
            a[mt][1] = pa[8 * SXP];
            a[mt][2] = pa[4];
            a[mt][3] = pa[8 * SXP + 4];
        }
        // B frags: b0 = Wp[kk0+ql][n], b1 = Wp[kk0+ql+4][n], n = wn*64+nt*8+qr
        uint32_t b[8][2];
#pragma unroll
        for (int nt = 0; nt < 8; nt++) {
            const uint32_t* pb = sB + (kk0 + ql) * SWP + wn * 64 + nt * 8 + qr;
            b[nt][0] = pb[0];
            b[nt][1] = pb[4 * SWP];
        }
#pragma unroll
        for (int mt = 0; mt < 2; mt++)
#pragma unroll
            for (int nt = 0; nt < 8; nt++) {
                float* c = acc[mt][nt];
                asm volatile(
                    "mma.sync.aligned.m16n8k16.row.col.f32.f16.f16.f32 "
                    "{%0,%1,%2,%3}, {%4,%5,%6,%7}, {%8,%9}, {%0,%1,%2,%3};"
                    : "+f"(c[0]), "+f"(c[1]), "+f"(c[2]), "+f"(c[3])
                    : "r"(a[mt][0]), "r"(a[mt][1]), "r"(a[mt][2]), "r"(a[mt][3]),
                      "r"(b[nt][0]), "r"(b[nt][1]));
            }
    }

    // ---- Store xl (fp16) + fused attention dots (fp32 accs) ----
    float ps[4], pd[4];
#pragma unroll
    for (int k = 0; k < 4; k++) { ps[k] = 0.f; pd[k] = 0.f; }

#pragma unroll
    for (int mt = 0; mt < 2; mt++) {
        int r_lo = row0 + wm * 32 + mt * 16 + qr;
#pragma unroll
        for (int nt = 0; nt < 8; nt++) {
            int col = wn * 64 + nt * 8 + 2 * ql;
            int cl = nt * 8 + 2 * ql;
            const float* c = acc[mt][nt];
            float a0s = att_src[wn * 64 + cl], a1s = att_src[wn * 64 + cl + 1];
            float a0d = att_dst[wn * 64 + cl], a1d = att_dst[wn * 64 + cl + 1];
            ps[mt * 2 + 0] += c[0] * a0s + c[1] * a1s;
            pd[mt * 2 + 0] += c[0] * a0d + c[1] * a1d;
            ps[mt * 2 + 1] += c[2] * a0s + c[3] * a1s;
            pd[mt * 2 + 1] += c[2] * a0d + c[3] * a1d;
            if (r_lo < n)
                *(__half2*)(g_xlh + (size_t)r_lo * HC + col) = __floats2half2_rn(c[0], c[1]);
            if (r_lo + 8 < n)
                *(__half2*)(g_xlh + (size_t)(r_lo + 8) * HC + col) = __floats2half2_rn(c[2], c[3]);
        }
    }

#pragma unroll
    for (int k = 0; k < 4; k++) {
#pragma unroll
        for (int off = 2; off > 0; off >>= 1) {
            ps[k] += __shfl_down_sync(0xffffffffu, ps[k], off, 4);
            pd[k] += __shfl_down_sync(0xffffffffu, pd[k], off, 4);
        }
    }
    if (ql == 0) {
#pragma unroll
        for (int mt = 0; mt < 2; mt++) {
            int r_lo = row0 + wm * 32 + mt * 16 + qr;
            if (r_lo < n) {
                g_asrc[r_lo * HEADS + wn] = ps[mt * 2 + 0];
                g_adst[r_lo * HEADS + wn] = pd[mt * 2 + 0];
            }
            if (r_lo + 8 < n) {
                g_asrc[(r_lo + 8) * HEADS + wn] = ps[mt * 2 + 1];
                g_adst[(r_lo + 8) * HEADS + wn] = pd[mt * 2 + 1];
            }
        }
    }
}

// ---------------------------------------------------------------------------
// 6. Aggregate v3, warp per destination node.
//    Pass 1: lane-parallel logits over all edges (4 heads), warp-max.
//    Pass 2: lane-parallel exp weights; inner channel-accumulate loop gets
//            src id + weight via SHFL (register latency, no L2 chain);
//            xl gather prefetched 2 deep. den via warp shfl-reduce.
// ---------------------------------------------------------------------------
__global__ void agg_kernel(const float* __restrict__ bias, float* __restrict__ out, int N) {
    int w = (blockIdx.x * blockDim.x + threadIdx.x) >> 5;
    int lane = threadIdx.x & 31;
    if (w >= N) return;

    const float* bp = bias + lane * 8;
    float4 b0 = *(const float4*)bp;
    float4 b1 = *(const float4*)(bp + 4);
    float* po = out + (size_t)w * HC + lane * 8;

    int beg = g_off[w];
    int end = g_off[w + 1];
    if (beg == end) {
        *(float4*)po = b0;
        *(float4*)(po + 4) = b1;
        return;
    }

    float4 ad4 = *(const float4*)(g_adst + w * HEADS);

    // ---- Pass 1: segment max (all heads), lanes parallel over edges ----
    float4 mx = make_float4(-FLT_MAX, -FLT_MAX, -FLT_MAX, -FLT_MAX);
    for (int base = beg; base < end; base += 32) {
        if (base + lane < end) {
            int s = g_srclist[base + lane];
            float4 as = *(const float4*)(g_asrc + s * HEADS);
            mx.x = fmaxf(mx.x, leaky(as.x + ad4.x));
            mx.y = fmaxf(mx.y, leaky(as.y + ad4.y));
            mx.z = fmaxf(mx.z, leaky(as.z + ad4.z));
            mx.w = fmaxf(mx.w, leaky(as.w + ad4.w));
        }
    }
#pragma unroll
    for (int off = 16; off > 0; off >>= 1) {
        mx.x = fmaxf(mx.x, __shfl_xor_sync(0xffffffffu, mx.x, off));
        mx.y = fmaxf(mx.y, __shfl_xor_sync(0xffffffffu, mx.y, off));
        mx.z = fmaxf(mx.z, __shfl_xor_sync(0xffffffffu, mx.z, off));
        mx.w = fmaxf(mx.w, __shfl_xor_sync(0xffffffffu, mx.w, off));
    }

    int h = lane >> 3;
    float4 den4 = make_float4(0.f, 0.f, 0.f, 0.f);
    float acc[8];
#pragma unroll
    for (int k = 0; k < 8; k++) acc[k] = 0.f;

    // ---- Pass 2: per-chunk exp weights + channel accumulate via shfl ----
    for (int base = beg; base < end; base += 32) {
        int c = min(end - base, 32);
        int sid = 0;
        float4 we4 = make_float4(0.f, 0.f, 0.f, 0.f);
        if (lane < c) {
            sid = g_srclist[base + lane];
            float4 as = *(const float4*)(g_asrc + sid * HEADS);
            we4.x = __expf(leaky(as.x + ad4.x) - mx.x);
            we4.y = __expf(leaky(as.y + ad4.y) - mx.y);
            we4.z = __expf(leaky(as.z + ad4.z) - mx.z);
            we4.w = __expf(leaky(as.w + ad4.w) - mx.w);
        }
        den4.x += we4.x; den4.y += we4.y; den4.z += we4.z; den4.w += we4.w;

        // prefetch 2 deep
        uint4 pk0 = make_uint4(0, 0, 0, 0), pk1 = make_uint4(0, 0, 0, 0);
        {
            int s0 = __shfl_sync(0xffffffffu, sid, 0);
            pk0 = *(const uint4*)(g_xlh + (size_t)s0 * HC + lane * 8);
            if (c > 1) {
                int s1 = __shfl_sync(0xffffffffu, sid, 1);
                pk1 = *(const uint4*)(g_xlh + (size_t)s1 * HC + lane * 8);
            }
        }
        for (int j = 0; j < c; j++) {
            uint4 pk2 = make_uint4(0, 0, 0, 0);
            if (j + 2 < c) {
                int s2 = __shfl_sync(0xffffffffu, sid, j + 2);
                pk2 = *(const uint4*)(g_xlh + (size_t)s2 * HC + lane * 8);
            }
            float wx = __shfl_sync(0xffffffffu, we4.x, j);
            float wy = __shfl_sync(0xffffffffu, we4.y, j);
            float wz = __shfl_sync(0xffffffffu, we4.z, j);
            float ww = __shfl_sync(0xffffffffu, we4.w, j);
            float we = (h == 0) ? wx : (h == 1) ? wy : (h == 2) ? wz : ww;

            float2 f0 = __half22float2(*(__half2*)&pk0.x);
            float2 f1 = __half22float2(*(__half2*)&pk0.y);
            float2 f2 = __half22float2(*(__half2*)&pk0.z);
            float2 f3 = __half22float2(*(__half2*)&pk0.w);
            acc[0] += we * f0.x;
            acc[1] += we * f0.y;
            acc[2] += we * f1.x;
            acc[3] += we * f1.y;
            acc[4] += we * f2.x;
            acc[5] += we * f2.y;
            acc[6] += we * f3.x;
            acc[7] += we * f3.y;

            pk0 = pk1; pk1 = pk2;
        }
    }

    // ---- den: warp-reduce per-lane partial sums ----
#pragma unroll
    for (int off = 16; off > 0; off >>= 1) {
        den4.x += __shfl_xor_sync(0xffffffffu, den4.x, off);
        den4.y += __shfl_xor_sync(0xffffffffu, den4.y, off);
        den4.z += __shfl_xor_sync(0xffffffffu, den4.z, off);
        den4.w += __shfl_xor_sync(0xffffffffu, den4.w, off);
    }
    float den = (h == 0) ? den4.x : (h == 1) ? den4.y : (h == 2) ? den4.z : den4.w;

    float inv = 1.f / (den + 1e-16f);
    float4 o0 = make_float4(acc[0] * inv + b0.x, acc[1] * inv + b0.y,
                            acc[2] * inv + b0.z, acc[3] * inv + b0.w);
    float4 o1 = make_float4(acc[4] * inv + b1.x, acc[5] * inv + b1.y,
                            acc[6] * inv + b1.z, acc[7] * inv + b1.w);
    *(float4*)po = o0;
    *(float4*)(po + 4) = o1;
}

// ---------------------------------------------------------------------------
// Launch.  gemm stays the 4th launch (ncu profiles launch #4).
// ---------------------------------------------------------------------------
extern "C" void kernel_launch(void* const* d_in, const int* in_sizes, int n_in,
                              void* d_out, int out_size) {
    const float* x        = (const float*)d_in[0];
    const void*  ei       = (const void*)d_in[1];
    const float* W        = (const float*)d_in[2];
    const float* att_src  = (const float*)d_in[3];
    const float* att_dst  = (const float*)d_in[4];
    const float* bias     = (const float*)d_in[5];
    float* out = (float*)d_out;

    int N = in_sizes[0] / D_IN;
    int E = in_sizes[1] / 2;

    init_kernel<<<(N + 255) / 256, 256>>>(ei, N);                 // 1
    count_kernel<<<(E / 2 + 256) / 256, 256>>>(ei, E);            // 2

    int nb = (N + SCAN_B - 1) / SCAN_B;   // 98 for N=100000
    scan1_kernel<<<nb, SCAN_B>>>(N);                              // 3

    size_t smem = ((size_t)64 * SXP + (size_t)32 * SWP) * 4;      // ~43 KB
    cudaFuncSetAttribute(gemm_kernel, cudaFuncAttributeMaxDynamicSharedMemorySize, (int)smem);
    gemm_kernel<<<(N + 63) / 64, 256, smem>>>(x, W, att_src, att_dst, N);  // 4 (profiled)

    scan2_kernel<<<1, 128>>>(nb, N, E);                           // 5
    scan3_kernel<<<nb, SCAN_B>>>(N);                              // 6
    scatter_kernel<<<(E / 2 + 256) / 256, 256>>>(ei, E);          // 7

    long long agg_threads = (long long)N * 32;
    agg_kernel<<<(int)((agg_threads + 255) / 256), 256>>>(bias, out, N);   // 8
}

// round 8
// speedup vs baseline: 1.3625x; 1.3625x over previous
#include <cuda_runtime.h>
#include <cuda_fp16.h>
#include <math.h>
#include <float.h>
#include <stdint.h>

// Problem constants (GAT_38585986187787)
#define MAX_NODES 100000
#define MAX_EDGES 1600000
#define D_IN 64
#define HEADS 4
#define HC 256   // HEADS * C_OUT
#define SCAN_B 1024
#define MAX_SCAN_BLOCKS 128

// smem strides (uint32 units), bank-conflict-free fragment loads
#define SAP 132  // agg tile: 132 % 32 == 4 -> bank = 4r + kk, distinct per 8x4 lanes
#define SWP 264  // W tile:   264 % 32 == 8 -> bank = 8kk + n, distinct per 4x8 lanes

// ---------------------------------------------------------------------------
// Device scratch
// ---------------------------------------------------------------------------
__device__ __half g_x16[(size_t)MAX_NODES * D_IN];  // 12.8 MB  x in fp16 (L2-resident)
__device__ __half g_agg[(size_t)MAX_NODES * HC];    // 51.2 MB  normalized weighted sums
__device__ float g_asrc[MAX_NODES * HEADS];         // 1.6 MB
__device__ float g_adst[MAX_NODES * HEADS];         // 1.6 MB
__device__ float g_was[HEADS * D_IN];               // W_h @ att_src_h
__device__ float g_wad[HEADS * D_IN];               // W_h @ att_dst_h
__device__ int   g_cnt[MAX_NODES];
__device__ int   g_off[MAX_NODES + 1];
__device__ int   g_cur[MAX_NODES];
__device__ int   g_srclist[MAX_EDGES];
__device__ int   g_bsum[MAX_SCAN_BLOCKS];
__device__ int   g_bpre[MAX_SCAN_BLOCKS];
__device__ int   g_is64;

__device__ __forceinline__ long long load_edge(const void* ei, int is64, size_t idx) {
    if (is64) return ((const long long*)ei)[idx];
    return (long long)(((const int*)ei)[idx]);
}

__device__ __forceinline__ float leaky(float v) {
    return (v >= 0.f) ? v : 0.2f * v;
}

// ---------------------------------------------------------------------------
// 1. Init: detect dtype, zero counters, block 0 computes projected att vecs
//    was[h][c] = sum_j W[c, h*64+j] * att_src[h][j]   (exact fp32)
// ---------------------------------------------------------------------------
__global__ void init_kernel(const void* ei, const float* __restrict__ W,
                            const float* __restrict__ att_src,
                            const float* __restrict__ att_dst, int n) {
    int idx = blockIdx.x * blockDim.x + threadIdx.x;
    if (idx == 0) {
        const unsigned long long* p = (const unsigned long long*)ei;
        bool ok = true;
#pragma unroll
        for (int i = 0; i < 16; i++) ok = ok && (p[i] < (unsigned long long)MAX_NODES);
        g_is64 = ok ? 1 : 0;
    }
    if (idx < n) g_cnt[idx] = 0;
    if (blockIdx.x == 0) {
        for (int o = threadIdx.x; o < 2 * HEADS * D_IN; o += blockDim.x) {
            int kind = o >> 8;           // 0: src, 1: dst
            int h = (o >> 6) & 3;
            int c = o & 63;
            const float* av = (kind ? att_dst : att_src) + h * 64;
            float s = 0.f;
#pragma unroll 8
            for (int j = 0; j < 64; j++) s += W[(size_t)c * HC + h * 64 + j] * av[j];
            if (kind) g_wad[h * 64 + c] = s;
            else      g_was[h * 64 + c] = s;
        }
    }
}

// ---------------------------------------------------------------------------
// 2. Count in-degrees (2 edges per thread)
// ---------------------------------------------------------------------------
__global__ void count_kernel(const void* __restrict__ ei, int E) {
    int e = (blockIdx.x * blockDim.x + threadIdx.x) * 2;
    if (e >= E) return;
    int is64 = g_is64;
    if (e + 1 < E) {
        int d0, d1;
        if (is64) {
            longlong2 p = *(const longlong2*)((const long long*)ei + (size_t)E + e);
            d0 = (int)p.x; d1 = (int)p.y;
        } else {
            int2 p = *(const int2*)((const int*)ei + (size_t)E + e);
            d0 = p.x; d1 = p.y;
        }
        atomicAdd(&g_cnt[d0], 1);
        atomicAdd(&g_cnt[d1], 1);
    } else {
        int d = (int)load_edge(ei, is64, (size_t)E + e);
        atomicAdd(&g_cnt[d], 1);
    }
}

// ---------------------------------------------------------------------------
// 3a. Block-local exclusive scan
// ---------------------------------------------------------------------------
__global__ void scan1_kernel(int N) {
    int t = threadIdx.x;
    int i = blockIdx.x * SCAN_B + t;
    int lane = t & 31, wid = t >> 5;

    int v = (i < N) ? g_cnt[i] : 0;
    int x = v;
#pragma unroll
    for (int off = 1; off < 32; off <<= 1) {
        int u = __shfl_up_sync(0xffffffffu, x, off);
        if (lane >= off) x += u;
    }
    __shared__ int wsum[32];
    if (lane == 31) wsum[wid] = x;
    __syncthreads();
    if (wid == 0) {
        int y = wsum[lane];
#pragma unroll
        for (int off = 1; off < 32; off <<= 1) {
            int u = __shfl_up_sync(0xffffffffu, y, off);
            if (lane >= off) y += u;
        }
        wsum[lane] = y;
    }
    __syncthreads();
    int base = (wid > 0) ? wsum[wid - 1] : 0;
    int incl = base + x;
    if (i < N) g_off[i] = incl - v;
    if (t == SCAN_B - 1) g_bsum[blockIdx.x] = incl;
}

// ---------------------------------------------------------------------------
// 4. Attention scores from x directly + fp16 conversion of x.
//    Warp per node: a_src[n,h] = x[n] . was_h  (exact math identity to ref).
// ---------------------------------------------------------------------------
__global__ void att_kernel(const float* __restrict__ x, int N) {
    int w = (blockIdx.x * blockDim.x + threadIdx.x) >> 5;
    int lane = threadIdx.x & 31;
    if (w >= N) return;

    float2 xv = *(const float2*)(x + (size_t)w * D_IN + lane * 2);
    *(__half2*)(g_x16 + (size_t)w * D_IN + lane * 2) = __floats2half2_rn(xv.x, xv.y);

    float ps[4], pd[4];
#pragma unroll
    for (int h = 0; h < 4; h++) {
        float2 ws = *(const float2*)(g_was + h * 64 + lane * 2);
        float2 wd = *(const float2*)(g_wad + h * 64 + lane * 2);
        ps[h] = xv.x * ws.x + xv.y * ws.y;
        pd[h] = xv.x * wd.x + xv.y * wd.y;
    }
#pragma unroll
    for (int off = 16; off > 0; off >>= 1) {
#pragma unroll
        for (int h = 0; h < 4; h++) {
            ps[h] += __shfl_xor_sync(0xffffffffu, ps[h], off);
            pd[h] += __shfl_xor_sync(0xffffffffu, pd[h], off);
        }
    }
    if (lane == 0) {
        *(float4*)(g_asrc + w * HEADS) = make_float4(ps[0], ps[1], ps[2], ps[3]);
        *(float4*)(g_adst + w * HEADS) = make_float4(pd[0], pd[1], pd[2], pd[3]);
    }
}

// ---------------------------------------------------------------------------
// 3b/3c. Scan block sums + add bases
// ---------------------------------------------------------------------------
__global__ void scan2_kernel(int nb, int N, int E) {
    int t = threadIdx.x, lane = t & 31, wid = t >> 5;
    int v = (t < nb) ? g_bsum[t] : 0;
    int x = v;
#pragma unroll
    for (int off = 1; off < 32; off <<= 1) {
        int u = __shfl_up_sync(0xffffffffu, x, off);
        if (lane >= off) x += u;
    }
    __shared__ int ws[4];
    __shared__ int wpre[4];
    if (lane == 31) ws[wid] = x;
    __syncthreads();
    if (t == 0) {
        int s = 0;
#pragma unroll
        for (int k = 0; k < 4; k++) { wpre[k] = s; s += ws[k]; }
    }
    __syncthreads();
    int incl = wpre[wid] + x;
    if (t < nb) g_bpre[t] = incl - v;
    if (t == 0) g_off[N] = E;
}

__global__ void scan3_kernel(int N) {
    int i = blockIdx.x * SCAN_B + threadIdx.x;
    if (i < N) {
        int o = g_off[i] + g_bpre[blockIdx.x];
        g_off[i] = o;
        g_cur[i] = o;
    }
}

// ---------------------------------------------------------------------------
// 5. Scatter src ids into CSR slots (2 edges per thread)
// ---------------------------------------------------------------------------
__global__ void scatter_kernel(const void* __restrict__ ei, int E) {
    int e = (blockIdx.x * blockDim.x + threadIdx.x) * 2;
    if (e >= E) return;
    int is64 = g_is64;
    if (e + 1 < E) {
        int s0, s1, d0, d1;
        if (is64) {
            longlong2 ps = *(const longlong2*)((const long long*)ei + e);
            longlong2 pd = *(const longlong2*)((const long long*)ei + (size_t)E + e);
            s0 = (int)ps.x; s1 = (int)ps.y; d0 = (int)pd.x; d1 = (int)pd.y;
        } else {
            int2 ps = *(const int2*)((const int*)ei + e);
            int2 pd = *(const int2*)((const int*)ei + (size_t)E + e);
            s0 = ps.x; s1 = ps.y; d0 = pd.x; d1 = pd.y;
        }
        int p0 = atomicAdd(&g_cur[d0], 1);
        int p1 = atomicAdd(&g_cur[d1], 1);
        g_srclist[p0] = s0;
        g_srclist[p1] = s1;
    } else {
        int s = (int)load_edge(ei, is64, e);
        int d = (int)load_edge(ei, is64, (size_t)E + e);
        int pos = atomicAdd(&g_cur[d], 1);
        g_srclist[pos] = s;
    }
}

// ---------------------------------------------------------------------------
// 6. Aggregate in x-space: agg[dst,h,:] = (1/den_h) * sum_e we_h * x16[src].
//    Warp per dst. Single pass (no max subtraction — logits are O(1), exp is
//    safe in fp32 and alpha ratios are identical). Per 32-edge chunk: lanes
//    stage sid + we4 to smem; serial inner loop gathers 4B/lane of x16
//    (128 B/edge coalesced, L2-resident) with 1-deep prefetch.
//    Lane owns channels 2*lane, 2*lane+1 for all 4 heads (8 acc regs).
// ---------------------------------------------------------------------------
__global__ void agg_kernel(int N) {
    __shared__ float4 swe[8][32];
    __shared__ int    ssid[8][32];
    int wl = threadIdx.x >> 5;
    int w = (blockIdx.x * blockDim.x + threadIdx.x) >> 5;
    int lane = threadIdx.x & 31;
    if (w >= N) return;

    __half2* arow = (__half2*)(g_agg + (size_t)w * HC);
    int beg = g_off[w];
    int end = g_off[w + 1];
    if (beg == end) {
        __half2 z = __floats2half2_rn(0.f, 0.f);
#pragma unroll
        for (int h = 0; h < 4; h++) arow[h * 32 + lane] = z;
        return;
    }

    float4 ad4 = *(const float4*)(g_adst + w * HEADS);
    float4 den4 = make_float4(0.f, 0.f, 0.f, 0.f);
    float acc[8];
#pragma unroll
    for (int k = 0; k < 8; k++) acc[k] = 0.f;

    for (int base = beg; base < end; base += 32) {
        int c = min(end - base, 32);
        if (lane < c) {
            int s = g_srclist[base + lane];
            float4 as = *(const float4*)(g_asrc + s * HEADS);
            float4 we;
            we.x = __expf(leaky(as.x + ad4.x));
            we.y = __expf(leaky(as.y + ad4.y));
            we.z = __expf(leaky(as.z + ad4.z));
            we.w = __expf(leaky(as.w + ad4.w));
            den4.x += we.x; den4.y += we.y; den4.z += we.z; den4.w += we.w;
            swe[wl][lane] = we;
            ssid[wl][lane] = s;
        }
        __syncwarp();

        uint32_t x0 = *(const uint32_t*)(g_x16 + (size_t)ssid[wl][0] * D_IN + lane * 2);
        for (int j = 0; j < c; j++) {
            uint32_t x1 = 0;
            if (j + 1 < c)
                x1 = *(const uint32_t*)(g_x16 + (size_t)ssid[wl][j + 1] * D_IN + lane * 2);
            float4 we = swe[wl][j];
            float2 xv = __half22float2(*(__half2*)&x0);
            acc[0] += we.x * xv.x; acc[1] += we.x * xv.y;
            acc[2] += we.y * xv.x; acc[3] += we.y * xv.y;
            acc[4] += we.z * xv.x; acc[5] += we.z * xv.y;
            acc[6] += we.w * xv.x; acc[7] += we.w * xv.y;
            x0 = x1;
        }
        __syncwarp();
    }

#pragma unroll
    for (int off = 16; off > 0; off >>= 1) {
        den4.x += __shfl_xor_sync(0xffffffffu, den4.x, off);
        den4.y += __shfl_xor_sync(0xffffffffu, den4.y, off);
        den4.z += __shfl_xor_sync(0xffffffffu, den4.z, off);
        den4.w += __shfl_xor_sync(0xffffffffu, den4.w, off);
    }
    float ix = 1.f / (den4.x + 1e-16f);
    float iy = 1.f / (den4.y + 1e-16f);
    float iz = 1.f / (den4.z + 1e-16f);
    float iw = 1.f / (den4.w + 1e-16f);
    arow[0 * 32 + lane] = __floats2half2_rn(acc[0] * ix, acc[1] * ix);
    arow[1 * 32 + lane] = __floats2half2_rn(acc[2] * iy, acc[3] * iy);
    arow[2 * 32 + lane] = __floats2half2_rn(acc[4] * iz, acc[5] * iz);
    arow[3 * 32 + lane] = __floats2half2_rn(acc[6] * iw, acc[7] * iw);
}

// ---------------------------------------------------------------------------
// 7. Output GEMM: out[n, h*64+j] = agg[n,h,:] . W[:, h*64+j] + bias.
//    Per-head [N,64]@[64,64]; fp16 MMA m16n8k16, fp32 acc.
//    Block 64 rows x 256 cols, 8 warps 2(M)x4(N=head).
// ---------------------------------------------------------------------------
__global__ void __launch_bounds__(256, 2)
gemm_out_kernel(const float* __restrict__ W, const float* __restrict__ bias,
                float* __restrict__ out, int n) {
    extern __shared__ uint32_t sm[];
    uint32_t* sA = sm;                 // 64 rows x SAP (agg, half2 packed)
    uint32_t* sB = sm + 64 * SAP;      // 32 kk x SWP (W, k-pairs packed)

    int t = threadIdx.x;
    int lane = t & 31;
    int wid = t >> 5;
    int wm = wid >> 2;
    int wn = wid & 3;          // head
    int row0 = blockIdx.x * 64;

    // ---- Stage agg tile (64 rows x 256 halves) ----
#pragma unroll
    for (int i = 0; i < 8; i++) {
        int idx = t + i * 256;             // uint4 index: 64 rows * 32 per row
        int r = idx >> 5, c4 = idx & 31;
        uint4 v = make_uint4(0, 0, 0, 0);
        if (row0 + r < n) v = *(const uint4*)(g_agg + (size_t)(row0 + r) * HC + c4 * 8);
        uint32_t* p = sA + r * SAP + c4 * 4;
        p[0] = v.x; p[1] = v.y; p[2] = v.z; p[3] = v.w;
    }

    // ---- Stage W -> Wp[kk][n] = half2(W[2kk][n], W[2kk+1][n]) ----
    __half* sBh = (__half*)sB;
#pragma unroll
    for (int i = 0; i < 16; i++) {
        int idx4 = t + i * 256;
        int k = idx4 >> 6, c = (idx4 & 63) * 4;
        float4 v = *(const float4*)(W + (size_t)k * HC + c);
        int base = ((k >> 1) * SWP + c) * 2 + (k & 1);
        sBh[base + 0] = __float2half_rn(v.x);
        sBh[base + 2] = __float2half_rn(v.y);
        sBh[base + 4] = __float2half_rn(v.z);
        sBh[base + 6] = __float2half_rn(v.w);
    }
    __syncthreads();

    float acc[2][8][4];
#pragma unroll
    for (int mt = 0; mt < 2; mt++)
#pragma unroll
        for (int nt = 0; nt < 8; nt++)
#pragma unroll
            for (int k = 0; k < 4; k++) acc[mt][nt][k] = 0.f;

    int qr = lane >> 2;
    int ql = lane & 3;

#pragma unroll
    for (int kc = 0; kc < 4; kc++) {
        int kk0 = kc * 8;
        uint32_t a[2][4];
#pragma unroll
        for (int mt = 0; mt < 2; mt++) {
            int rb = wm * 32 + mt * 16 + qr;
            const uint32_t* pa = sA + rb * SAP + wn * 32 + kk0 + ql;
            a[mt][0] = pa[0];
            a[mt][1] = pa[8 * SAP];
            a[mt][2] = pa[4];
            a[mt][3] = pa[8 * SAP + 4];
        }
        uint32_t b[8][2];
#pragma unroll
        for (int nt = 0; nt < 8; nt++) {
            const uint32_t* pb = sB + (kk0 + ql) * SWP + wn * 64 + nt * 8 + qr;
            b[nt][0] = pb[0];
            b[nt][1] = pb[4 * SWP];
        }
#pragma unroll
        for (int mt = 0; mt < 2; mt++)
#pragma unroll
            for (int nt = 0; nt < 8; nt++) {
                float* c = acc[mt][nt];
                asm volatile(
                    "mma.sync.aligned.m16n8k16.row.col.f32.f16.f16.f32 "
                    "{%0,%1,%2,%3}, {%4,%5,%6,%7}, {%8,%9}, {%0,%1,%2,%3};"
                    : "+f"(c[0]), "+f"(c[1]), "+f"(c[2]), "+f"(c[3])
                    : "r"(a[mt][0]), "r"(a[mt][1]), "r"(a[mt][2]), "r"(a[mt][3]),
                      "r"(b[nt][0]), "r"(b[nt][1]));
            }
    }

    // ---- Epilogue: + bias, store fp32 ----
#pragma unroll
    for (int mt = 0; mt < 2; mt++) {
        int r_lo = row0 + wm * 32 + mt * 16 + qr;
#pragma unroll
        for (int nt = 0; nt < 8; nt++) {
            int col = wn * 64 + nt * 8 + 2 * ql;
            float2 bb = *(const float2*)(bias + col);
            const float* c = acc[mt][nt];
            if (r_lo < n)
                *(float2*)(out + (size_t)r_lo * HC + col) = make_float2(c[0] + bb.x, c[1] + bb.y);
            if (r_lo + 8 < n)
                *(float2*)(out + (size_t)(r_lo + 8) * HC + col) = make_float2(c[2] + bb.x, c[3] + bb.y);
        }
    }
}

// ---------------------------------------------------------------------------
// Launch.  att_kernel is the 4th launch (ncu profiles launch #4).
// ---------------------------------------------------------------------------
extern "C" void kernel_launch(void* const* d_in, const int* in_sizes, int n_in,
                              void* d_out, int out_size) {
    const float* x        = (const float*)d_in[0];
    const void*  ei       = (const void*)d_in[1];
    const float* W        = (const float*)d_in[2];
    const float* att_src  = (const float*)d_in[3];
    const float* att_dst  = (const float*)d_in[4];
    const float* bias     = (const float*)d_in[5];
    float* out = (float*)d_out;

    int N = in_sizes[0] / D_IN;
    int E = in_sizes[1] / 2;

    init_kernel<<<(N + 255) / 256, 256>>>(ei, W, att_src, att_dst, N);  // 1
    count_kernel<<<(E / 2 + 256) / 256, 256>>>(ei, E);                  // 2

    int nb = (N + SCAN_B - 1) / SCAN_B;
    scan1_kernel<<<nb, SCAN_B>>>(N);                                    // 3

    att_kernel<<<(N * 32 + 255) / 256, 256>>>(x, N);                    // 4 (profiled)

    scan2_kernel<<<1, 128>>>(nb, N, E);                                 // 5
    scan3_kernel<<<nb, SCAN_B>>>(N);                                    // 6
    scatter_kernel<<<(E / 2 + 256) / 256, 256>>>(ei, E);                // 7

    long long agg_threads = (long long)N * 32;
    agg_kernel<<<(int)((agg_threads + 255) / 256), 256>>>(N);           // 8

    size_t smem = ((size_t)64 * SAP + (size_t)32 * SWP) * 4;            // ~66 KB
    cudaFuncSetAttribute(gemm_out_kernel, cudaFuncAttributeMaxDynamicSharedMemorySize, (int)smem);
    gemm_out_kernel<<<(N + 63) / 64, 256, smem>>>(W, bias, out, N);     // 9
}

// round 9
// speedup vs baseline: 1.4538x; 1.0670x over previous
#include <cuda_runtime.h>
#include <cuda_fp16.h>
#include <math.h>
#include <float.h>
#include <stdint.h>

// Problem constants (GAT_38585986187787)
#define MAX_NODES 100000
#define MAX_EDGES 1600000
#define D_IN 64
#define HEADS 4
#define HC 256   // HEADS * C_OUT
#define SCAN_B 1024
#define MAX_SCAN_BLOCKS 128

#define SAP 132   // agg smem row stride (uint32): 132%32=4 -> 4-bank row spacing
#define SWN 264   // W smem row stride (halves):  528B/row -> 4-bank row spacing

// ---------------------------------------------------------------------------
// Device scratch
// ---------------------------------------------------------------------------
__device__ __half g_x16[(size_t)MAX_NODES * D_IN];  // 12.8 MB  x in fp16 (L2-resident)
__device__ __half g_agg[(size_t)MAX_NODES * HC];    // 51.2 MB  normalized weighted sums
__device__ float g_asrc[MAX_NODES * HEADS];
__device__ float g_adst[MAX_NODES * HEADS];
__device__ float g_was[HEADS * D_IN];               // W_h @ att_src_h
__device__ float g_wad[HEADS * D_IN];               // W_h @ att_dst_h
__device__ int   g_cnt[MAX_NODES];
__device__ int   g_off[MAX_NODES + 1];
__device__ int   g_cur[MAX_NODES];
__device__ int   g_srclist[MAX_EDGES];
__device__ int   g_bsum[MAX_SCAN_BLOCKS];
__device__ int   g_bpre[MAX_SCAN_BLOCKS];
__device__ int   g_is64;

__device__ __forceinline__ long long load_edge(const void* ei, int is64, size_t idx) {
    if (is64) return ((const long long*)ei)[idx];
    return (long long)(((const int*)ei)[idx]);
}

__device__ __forceinline__ float leaky(float v) {
    return (v >= 0.f) ? v : 0.2f * v;
}

// ---------------------------------------------------------------------------
// 1. Init: detect dtype, zero counters, block 0 computes projected att vecs
// ---------------------------------------------------------------------------
__global__ void init_kernel(const void* ei, const float* __restrict__ W,
                            const float* __restrict__ att_src,
                            const float* __restrict__ att_dst, int n) {
    int idx = blockIdx.x * blockDim.x + threadIdx.x;
    if (idx == 0) {
        const unsigned long long* p = (const unsigned long long*)ei;
        bool ok = true;
#pragma unroll
        for (int i = 0; i < 16; i++) ok = ok && (p[i] < (unsigned long long)MAX_NODES);
        g_is64 = ok ? 1 : 0;
    }
    if (idx < n) g_cnt[idx] = 0;
    if (blockIdx.x == 0) {
        for (int o = threadIdx.x; o < 2 * HEADS * D_IN; o += blockDim.x) {
            int kind = o >> 8;
            int h = (o >> 6) & 3;
            int c = o & 63;
            const float* av = (kind ? att_dst : att_src) + h * 64;
            float s = 0.f;
#pragma unroll 8
            for (int j = 0; j < 64; j++) s += W[(size_t)c * HC + h * 64 + j] * av[j];
            if (kind) g_wad[h * 64 + c] = s;
            else      g_was[h * 64 + c] = s;
        }
    }
}

// ---------------------------------------------------------------------------
// 2. Count in-degrees (4 edges per thread, vectorized)
// ---------------------------------------------------------------------------
__global__ void count_kernel(const void* __restrict__ ei, int E) {
    int e = (blockIdx.x * blockDim.x + threadIdx.x) * 4;
    if (e >= E) return;
    int is64 = g_is64;
    if (e + 3 < E) {
        int d[4];
        if (is64) {
            longlong2 p0 = *(const longlong2*)((const long long*)ei + (size_t)E + e);
            longlong2 p1 = *(const longlong2*)((const long long*)ei + (size_t)E + e + 2);
            d[0] = (int)p0.x; d[1] = (int)p0.y; d[2] = (int)p1.x; d[3] = (int)p1.y;
        } else {
            int4 p = *(const int4*)((const int*)ei + (size_t)E + e);
            d[0] = p.x; d[1] = p.y; d[2] = p.z; d[3] = p.w;
        }
#pragma unroll
        for (int k = 0; k < 4; k++) atomicAdd(&g_cnt[d[k]], 1);
    } else {
        for (int k = e; k < E; k++)
            atomicAdd(&g_cnt[(int)load_edge(ei, is64, (size_t)E + k)], 1);
    }
}

// ---------------------------------------------------------------------------
// 3a. Block-local exclusive scan
// ---------------------------------------------------------------------------
__global__ void scan1_kernel(int N) {
    int t = threadIdx.x;
    int i = blockIdx.x * SCAN_B + t;
    int lane = t & 31, wid = t >> 5;

    int v = (i < N) ? g_cnt[i] : 0;
    int x = v;
#pragma unroll
    for (int off = 1; off < 32; off <<= 1) {
        int u = __shfl_up_sync(0xffffffffu, x, off);
        if (lane >= off) x += u;
    }
    __shared__ int wsum[32];
    if (lane == 31) wsum[wid] = x;
    __syncthreads();
    if (wid == 0) {
        int y = wsum[lane];
#pragma unroll
        for (int off = 1; off < 32; off <<= 1) {
            int u = __shfl_up_sync(0xffffffffu, y, off);
            if (lane >= off) y += u;
        }
        wsum[lane] = y;
    }
    __syncthreads();
    int base = (wid > 0) ? wsum[wid - 1] : 0;
    int incl = base + x;
    if (i < N) g_off[i] = incl - v;
    if (t == SCAN_B - 1) g_bsum[blockIdx.x] = incl;
}

// ---------------------------------------------------------------------------
// 4. Attention scores + fp16 convert. 4 nodes per warp, 8-lane groups.
//    Lane owns 8 channels; 3-level width-8 shfl reduction.
// ---------------------------------------------------------------------------
__global__ void att_kernel(const float* __restrict__ x, int N) {
    int gw = (blockIdx.x * blockDim.x + threadIdx.x) >> 5;
    int lane = threadIdx.x & 31;
    int g = lane >> 3, l8 = lane & 7;
    int node = gw * 4 + g;
    if (node >= N) return;

    const float* xr = x + (size_t)node * D_IN + l8 * 8;
    float4 v0 = *(const float4*)xr;
    float4 v1 = *(const float4*)(xr + 4);

    // fp16 convert (one 16B store per lane)
    __half2 h0 = __floats2half2_rn(v0.x, v0.y);
    __half2 h1 = __floats2half2_rn(v0.z, v0.w);
    __half2 h2 = __floats2half2_rn(v1.x, v1.y);
    __half2 h3 = __floats2half2_rn(v1.z, v1.w);
    uint4 pk = make_uint4(*(uint32_t*)&h0, *(uint32_t*)&h1, *(uint32_t*)&h2, *(uint32_t*)&h3);
    *(uint4*)(g_x16 + (size_t)node * D_IN + l8 * 8) = pk;

    float ps[4], pd[4];
#pragma unroll
    for (int h = 0; h < 4; h++) {
        const float* ws = g_was + h * 64 + l8 * 8;
        const float* wd = g_wad + h * 64 + l8 * 8;
        float4 s0 = *(const float4*)ws, s1 = *(const float4*)(ws + 4);
        float4 d0 = *(const float4*)wd, d1 = *(const float4*)(wd + 4);
        ps[h] = v0.x * s0.x + v0.y * s0.y + v0.z * s0.z + v0.w * s0.w
              + v1.x * s1.x + v1.y * s1.y + v1.z * s1.z + v1.w * s1.w;
        pd[h] = v0.x * d0.x + v0.y * d0.y + v0.z * d0.z + v0.w * d0.w
              + v1.x * d1.x + v1.y * d1.y + v1.z * d1.z + v1.w * d1.w;
    }
#pragma unroll
    for (int off = 4; off > 0; off >>= 1) {
#pragma unroll
        for (int h = 0; h < 4; h++) {
            ps[h] += __shfl_xor_sync(0xffffffffu, ps[h], off, 8);
            pd[h] += __shfl_xor_sync(0xffffffffu, pd[h], off, 8);
        }
    }
    if (l8 == 0) {
        *(float4*)(g_asrc + node * HEADS) = make_float4(ps[0], ps[1], ps[2], ps[3]);
        *(float4*)(g_adst + node * HEADS) = make_float4(pd[0], pd[1], pd[2], pd[3]);
    }
}

// ---------------------------------------------------------------------------
// 3b/3c. Scan block sums + add bases
// ---------------------------------------------------------------------------
__global__ void scan2_kernel(int nb, int N, int E) {
    int t = threadIdx.x, lane = t & 31, wid = t >> 5;
    int v = (t < nb) ? g_bsum[t] : 0;
    int x = v;
#pragma unroll
    for (int off = 1; off < 32; off <<= 1) {
        int u = __shfl_up_sync(0xffffffffu, x, off);
        if (lane >= off) x += u;
    }
    __shared__ int ws[4];
    __shared__ int wpre[4];
    if (lane == 31) ws[wid] = x;
    __syncthreads();
    if (t == 0) {
        int s = 0;
#pragma unroll
        for (int k = 0; k < 4; k++) { wpre[k] = s; s += ws[k]; }
    }
    __syncthreads();
    int incl = wpre[wid] + x;
    if (t < nb) g_bpre[t] = incl - v;
    if (t == 0) g_off[N] = E;
}

__global__ void scan3_kernel(int N) {
    int i = blockIdx.x * SCAN_B + threadIdx.x;
    if (i < N) {
        int o = g_off[i] + g_bpre[blockIdx.x];
        g_off[i] = o;
        g_cur[i] = o;
    }
}

// ---------------------------------------------------------------------------
// 5. Scatter src ids into CSR slots (2 edges per thread)
// ---------------------------------------------------------------------------
__global__ void scatter_kernel(const void* __restrict__ ei, int E) {
    int e = (blockIdx.x * blockDim.x + threadIdx.x) * 2;
    if (e >= E) return;
    int is64 = g_is64;
    if (e + 1 < E) {
        int s0, s1, d0, d1;
        if (is64) {
            longlong2 ps = *(const longlong2*)((const long long*)ei + e);
            longlong2 pd = *(const longlong2*)((const long long*)ei + (size_t)E + e);
            s0 = (int)ps.x; s1 = (int)ps.y; d0 = (int)pd.x; d1 = (int)pd.y;
        } else {
            int2 ps = *(const int2*)((const int*)ei + e);
            int2 pd = *(const int2*)((const int*)ei + (size_t)E + e);
            s0 = ps.x; s1 = ps.y; d0 = pd.x; d1 = pd.y;
        }
        int p0 = atomicAdd(&g_cur[d0], 1);
        int p1 = atomicAdd(&g_cur[d1], 1);
        g_srclist[p0] = s0;
        g_srclist[p1] = s1;
    } else {
        int s = (int)load_edge(ei, is64, e);
        int d = (int)load_edge(ei, is64, (size_t)E + e);
        int pos = atomicAdd(&g_cur[d], 1);
        g_srclist[pos] = s;
    }
}

// ---------------------------------------------------------------------------
// 6. Aggregate in x-space (unchanged from r8 — known good).
// ---------------------------------------------------------------------------
__global__ void agg_kernel(int N) {
    __shared__ float4 swe[8][32];
    __shared__ int    ssid[8][32];
    int wl = threadIdx.x >> 5;
    int w = (blockIdx.x * blockDim.x + threadIdx.x) >> 5;
    int lane = threadIdx.x & 31;
    if (w >= N) return;

    __half2* arow = (__half2*)(g_agg + (size_t)w * HC);
    int beg = g_off[w];
    int end = g_off[w + 1];
    if (beg == end) {
        __half2 z = __floats2half2_rn(0.f, 0.f);
#pragma unroll
        for (int h = 0; h < 4; h++) arow[h * 32 + lane] = z;
        return;
    }

    float4 ad4 = *(const float4*)(g_adst + w * HEADS);
    float4 den4 = make_float4(0.f, 0.f, 0.f, 0.f);
    float acc[8];
#pragma unroll
    for (int k = 0; k < 8; k++) acc[k] = 0.f;

    for (int base = beg; base < end; base += 32) {
        int c = min(end - base, 32);
        if (lane < c) {
            int s = g_srclist[base + lane];
            float4 as = *(const float4*)(g_asrc + s * HEADS);
            float4 we;
            we.x = __expf(leaky(as.x + ad4.x));
            we.y = __expf(leaky(as.y + ad4.y));
            we.z = __expf(leaky(as.z + ad4.z));
            we.w = __expf(leaky(as.w + ad4.w));
            den4.x += we.x; den4.y += we.y; den4.z += we.z; den4.w += we.w;
            swe[wl][lane] = we;
            ssid[wl][lane] = s;
        }
        __syncwarp();

        uint32_t x0 = *(const uint32_t*)(g_x16 + (size_t)ssid[wl][0] * D_IN + lane * 2);
        for (int j = 0; j < c; j++) {
            uint32_t x1 = 0;
            if (j + 1 < c)
                x1 = *(const uint32_t*)(g_x16 + (size_t)ssid[wl][j + 1] * D_IN + lane * 2);
            float4 we = swe[wl][j];
            float2 xv = __half22float2(*(__half2*)&x0);
            acc[0] += we.x * xv.x; acc[1] += we.x * xv.y;
            acc[2] += we.y * xv.x; acc[3] += we.y * xv.y;
            acc[4] += we.z * xv.x; acc[5] += we.z * xv.y;
            acc[6] += we.w * xv.x; acc[7] += we.w * xv.y;
            x0 = x1;
        }
        __syncwarp();
    }

#pragma unroll
    for (int off = 16; off > 0; off >>= 1) {
        den4.x += __shfl_xor_sync(0xffffffffu, den4.x, off);
        den4.y += __shfl_xor_sync(0xffffffffu, den4.y, off);
        den4.z += __shfl_xor_sync(0xffffffffu, den4.z, off);
        den4.w += __shfl_xor_sync(0xffffffffu, den4.w, off);
    }
    float ix = 1.f / (den4.x + 1e-16f);
    float iy = 1.f / (den4.y + 1e-16f);
    float iz = 1.f / (den4.z + 1e-16f);
    float iw = 1.f / (den4.w + 1e-16f);
    arow[0 * 32 + lane] = __floats2half2_rn(acc[0] * ix, acc[1] * ix);
    arow[1 * 32 + lane] = __floats2half2_rn(acc[2] * iy, acc[3] * iy);
    arow[2 * 32 + lane] = __floats2half2_rn(acc[4] * iz, acc[5] * iz);
    arow[3 * 32 + lane] = __floats2half2_rn(acc[6] * iw, acc[7] * iw);
}

// ---------------------------------------------------------------------------
// 7. Output GEMM with ldmatrix fragment loads.
//    A: sA[r][half] row-major, ldmatrix.x4 (16x16 b16 tile).
//    B: W restaged [k][n] halves, ldmatrix.x4.trans (two 8x8 pairs / call).
// ---------------------------------------------------------------------------
__global__ void __launch_bounds__(256, 2)
gemm_out_kernel(const float* __restrict__ W, const float* __restrict__ bias,
                float* __restrict__ out, int n) {
    extern __shared__ uint32_t sm[];
    uint32_t* sA = sm;                       // 64 rows x SAP uint32
    __half*  sBh = (__half*)(sm + 64 * SAP); // 64 k-rows x SWN halves

    int t = threadIdx.x;
    int lane = t & 31;
    int wid = t >> 5;
    int wm = wid >> 2;
    int wn = wid & 3;          // head
    int row0 = blockIdx.x * 64;

    // ---- Stage agg tile ----
#pragma unroll
    for (int i = 0; i < 8; i++) {
        int idx = t + i * 256;
        int r = idx >> 5, c4 = idx & 31;
        uint4 v = make_uint4(0, 0, 0, 0);
        if (row0 + r < n) v = *(const uint4*)(g_agg + (size_t)(row0 + r) * HC + c4 * 8);
        uint32_t* p = sA + r * SAP + c4 * 4;
        p[0] = v.x; p[1] = v.y; p[2] = v.z; p[3] = v.w;
    }

    // ---- Stage W as [k][n] halves ----
#pragma unroll
    for (int i = 0; i < 16; i++) {
        int idx4 = t + i * 256;
        int k = idx4 >> 6, c = (idx4 & 63) * 4;
        float4 v = *(const float4*)(W + (size_t)k * HC + c);
        __half2* q = (__half2*)(sBh + k * SWN + c);
        q[0] = __floats2half2_rn(v.x, v.y);
        q[1] = __floats2half2_rn(v.z, v.w);
    }
    __syncthreads();

    uint32_t smem_base = (uint32_t)__cvta_generic_to_shared(sm);
    uint32_t sB_base = smem_base + 64 * SAP * 4;

    // ldmatrix lane addressing
    int l8 = lane & 7;
    int lrow8 = (lane >> 3) & 1;   // +8 rows for matrices 1,3
    int lk8 = (lane >> 4) & 1;     // +8 k (or +8 n) for matrices 2,3

    // A: addr(mt) = row(rb0 + l8 + lrow8*8) * SAP*4 + (wn*64 + kc*16 + lk8*8)*2
    uint32_t aAddr[2];
#pragma unroll
    for (int mt = 0; mt < 2; mt++) {
        int r = wm * 32 + mt * 16 + l8 + lrow8 * 8;
        aAddr[mt] = smem_base + r * (SAP * 4) + (wn * 64 + lk8 * 8) * 2;
    }
    // B: addr(ntp) = krow(kc*16 + l8 + lrow8*8) * SWN*2 + (wn*64 + ntp*16 + lk8*8)*2
    uint32_t bAddr[4];
#pragma unroll
    for (int ntp = 0; ntp < 4; ntp++) {
        int krow = l8 + lrow8 * 8;
        bAddr[ntp] = sB_base + krow * (SWN * 2) + (wn * 64 + ntp * 16 + lk8 * 8) * 2;
    }

    float acc[2][8][4];
#pragma unroll
    for (int mt = 0; mt < 2; mt++)
#pragma unroll
        for (int nt = 0; nt < 8; nt++)
#pragma unroll
            for (int k = 0; k < 4; k++) acc[mt][nt][k] = 0.f;

#pragma unroll
    for (int kc = 0; kc < 4; kc++) {
        uint32_t a[2][4];
#pragma unroll
        for (int mt = 0; mt < 2; mt++) {
            asm volatile(
                "ldmatrix.sync.aligned.m8n8.x4.shared.b16 {%0,%1,%2,%3}, [%4];"
                : "=r"(a[mt][0]), "=r"(a[mt][1]), "=r"(a[mt][2]), "=r"(a[mt][3])
                : "r"(aAddr[mt] + kc * 32));
        }
        uint32_t b[4][4];   // b[ntp] = {b(2ntp,0), b(2ntp,1), b(2ntp+1,0), b(2ntp+1,1)}
#pragma unroll
        for (int ntp = 0; ntp < 4; ntp++) {
            asm volatile(
                "ldmatrix.sync.aligned.m8n8.x4.trans.shared.b16 {%0,%1,%2,%3}, [%4];"
                : "=r"(b[ntp][0]), "=r"(b[ntp][1]), "=r"(b[ntp][2]), "=r"(b[ntp][3])
                : "r"(bAddr[ntp] + kc * 16 * (SWN * 2)));
        }
#pragma unroll
        for (int mt = 0; mt < 2; mt++)
#pragma unroll
            for (int nt = 0; nt < 8; nt++) {
                float* c = acc[mt][nt];
                uint32_t b0 = b[nt >> 1][(nt & 1) * 2 + 0];
                uint32_t b1 = b[nt >> 1][(nt & 1) * 2 + 1];
                asm volatile(
                    "mma.sync.aligned.m16n8k16.row.col.f32.f16.f16.f32 "
                    "{%0,%1,%2,%3}, {%4,%5,%6,%7}, {%8,%9}, {%0,%1,%2,%3};"
                    : "+f"(c[0]), "+f"(c[1]), "+f"(c[2]), "+f"(c[3])
                    : "r"(a[mt][0]), "r"(a[mt][1]), "r"(a[mt][2]), "r"(a[mt][3]),
                      "r"(b0), "r"(b1));
            }
    }

    int qr = lane >> 2;
    int ql = lane & 3;
#pragma unroll
    for (int mt = 0; mt < 2; mt++) {
        int r_lo = row0 + wm * 32 + mt * 16 + qr;
#pragma unroll
        for (int nt = 0; nt < 8; nt++) {
            int col = wn * 64 + nt * 8 + 2 * ql;
            float2 bb = *(const float2*)(bias + col);
            const float* c = acc[mt][nt];
            if (r_lo < n)
                *(float2*)(out + (size_t)r_lo * HC + col) = make_float2(c[0] + bb.x, c[1] + bb.y);
            if (r_lo + 8 < n)
                *(float2*)(out + (size_t)(r_lo + 8) * HC + col) = make_float2(c[2] + bb.x, c[3] + bb.y);
        }
    }
}

// ---------------------------------------------------------------------------
// Launch.  att_kernel is the 4th launch (ncu profiles launch #4).
// ---------------------------------------------------------------------------
extern "C" void kernel_launch(void* const* d_in, const int* in_sizes, int n_in,
                              void* d_out, int out_size) {
    const float* x        = (const float*)d_in[0];
    const void*  ei       = (const void*)d_in[1];
    const float* W        = (const float*)d_in[2];
    const float* att_src  = (const float*)d_in[3];
    const float* att_dst  = (const float*)d_in[4];
    const float* bias     = (const float*)d_in[5];
    float* out = (float*)d_out;

    int N = in_sizes[0] / D_IN;
    int E = in_sizes[1] / 2;

    init_kernel<<<(N + 255) / 256, 256>>>(ei, W, att_src, att_dst, N);  // 1
    count_kernel<<<(E / 4 + 256) / 256, 256>>>(ei, E);                  // 2

    int nb = (N + SCAN_B - 1) / SCAN_B;
    scan1_kernel<<<nb, SCAN_B>>>(N);                                    // 3

    int att_warps = (N + 3) / 4;
    att_kernel<<<(att_warps * 32 + 255) / 256, 256>>>(x, N);            // 4 (profiled)

    scan2_kernel<<<1, 128>>>(nb, N, E);                                 // 5
    scan3_kernel<<<nb, SCAN_B>>>(N);                                    // 6
    scatter_kernel<<<(E / 2 + 256) / 256, 256>>>(ei, E);                // 7

    long long agg_threads = (long long)N * 32;
    agg_kernel<<<(int)((agg_threads + 255) / 256), 256>>>(N);           // 8

    size_t smem = (size_t)64 * SAP * 4 + (size_t)64 * SWN * 2;          // 66 KB
    cudaFuncSetAttribute(gemm_out_kernel, cudaFuncAttributeMaxDynamicSharedMemorySize, (int)smem);
    gemm_out_kernel<<<(N + 63) / 64, 256, smem>>>(W, bias, out, N);     // 9
}